// round 1
// baseline (speedup 1.0000x reference)
#include <cuda_runtime.h>
#include <cstdint>

#define D        128
#define CD       3
#define NLAYERS  3
#define MAXN     65536

// ---------------- scratch (no allocations allowed) ----------------
__device__ float g_agg[(size_t)MAXN * D];
__device__ float g_x  [(size_t)MAXN * D];
__device__ float g_deg[MAXN];

// ---------------- degree count ----------------
__global__ void count_deg_kernel(const int* __restrict__ dst, float* __restrict__ deg, int E) {
    int i = blockIdx.x * blockDim.x + threadIdx.x;
    if (i < E) atomicAdd(&deg[dst[i]], 1.0f);
}

// ---------------- R init (identity) ----------------
__global__ void init_R_kernel(float* __restrict__ R, int n) {
    int i = blockIdx.x * blockDim.x + threadIdx.x;
    if (i < n) {
        float* r = R + (size_t)i * 9;
        r[0] = 1.f; r[1] = 0.f; r[2] = 0.f;
        r[3] = 0.f; r[4] = 1.f; r[5] = 0.f;
        r[6] = 0.f; r[7] = 0.f; r[8] = 1.f;
    }
}

// ---------------- scatter-add: agg[dst] += x[src] (warp per edge) ----------------
__global__ void scatter_kernel(const float4* __restrict__ x, const int* __restrict__ src,
                               const int* __restrict__ dst, float4* __restrict__ agg, int E) {
    int idx  = blockIdx.x * blockDim.x + threadIdx.x;
    int e    = idx >> 5;
    int lane = idx & 31;
    if (e >= E) return;
    int s = __ldg(&src[e]);
    int d = __ldg(&dst[e]);
    float4 v = __ldg(&x[(size_t)s * 32 + lane]);
    atomicAdd(&agg[(size_t)d * 32 + lane], v);   // sm_90+ vector atomic
}

// ---------------- GEMM: out = A(n x 128) @ W(128 x 128) + (deg? deg[r]*bias : bias) ----------------
#define BK 32
__global__ __launch_bounds__(256) void gemm_kernel(
        const float* __restrict__ A, const float* __restrict__ W,
        const float* __restrict__ bias, const float* __restrict__ deg,
        float* __restrict__ out, int n) {
    __shared__ float sA[BK][D + 4];   // transposed: sA[k][r]
    __shared__ float sW[BK][D];

    int t    = threadIdx.x;
    int row0 = blockIdx.x * 128;
    int tx   = t & 15;        // col group
    int ty   = t >> 4;        // row group
    int rb   = ty * 8;
    int cb   = tx * 8;

    float acc[8][8];
#pragma unroll
    for (int i = 0; i < 8; i++)
#pragma unroll
        for (int j = 0; j < 8; j++) acc[i][j] = 0.f;

    // loader indices
    int la_k = (t & 7) * 4;   // k offset (0..28 step 4)
    int la_r = t >> 3;        // 0..31
    int lw_k = t >> 3;        // 0..31
    int lw_c = (t & 7) * 4;   // 0..28 step 4

#pragma unroll 1
    for (int k0 = 0; k0 < D; k0 += BK) {
        // load A chunk (BK x 128), transposed into sA
#pragma unroll
        for (int rr = 0; rr < 128; rr += 32) {
            int rloc = la_r + rr;
            int rg   = row0 + rloc;
            float4 v = make_float4(0.f, 0.f, 0.f, 0.f);
            if (rg < n) v = *(const float4*)&A[(size_t)rg * D + k0 + la_k];
            sA[la_k + 0][rloc] = v.x;
            sA[la_k + 1][rloc] = v.y;
            sA[la_k + 2][rloc] = v.z;
            sA[la_k + 3][rloc] = v.w;
        }
        // load W chunk (BK x 128)
#pragma unroll
        for (int q = 0; q < 4; q++) {
            int c = lw_c + q * 32;
            *(float4*)&sW[lw_k][c] = *(const float4*)&W[(size_t)(k0 + lw_k) * D + c];
        }
        __syncthreads();

#pragma unroll
        for (int kk = 0; kk < BK; kk++) {
            float a[8], b[8];
            *(float4*)&a[0] = *(const float4*)&sA[kk][rb];
            *(float4*)&a[4] = *(const float4*)&sA[kk][rb + 4];
            *(float4*)&b[0] = *(const float4*)&sW[kk][cb];
            *(float4*)&b[4] = *(const float4*)&sW[kk][cb + 4];
#pragma unroll
            for (int i = 0; i < 8; i++)
#pragma unroll
                for (int j = 0; j < 8; j++) acc[i][j] += a[i] * b[j];
        }
        __syncthreads();
    }

    float bfrag[8];
#pragma unroll
    for (int j = 0; j < 8; j++) bfrag[j] = bias[cb + j];

#pragma unroll
    for (int i = 0; i < 8; i++) {
        int r = row0 + rb + i;
        if (r < n) {
            float f = deg ? deg[r] : 1.0f;
            float4 o0, o1;
            o0.x = acc[i][0] + f * bfrag[0];
            o0.y = acc[i][1] + f * bfrag[1];
            o0.z = acc[i][2] + f * bfrag[2];
            o0.w = acc[i][3] + f * bfrag[3];
            o1.x = acc[i][4] + f * bfrag[4];
            o1.y = acc[i][5] + f * bfrag[5];
            o1.z = acc[i][6] + f * bfrag[6];
            o1.w = acc[i][7] + f * bfrag[7];
            *(float4*)&out[(size_t)r * D + cb]     = o0;
            *(float4*)&out[(size_t)r * D + cb + 4] = o1;
        }
    }
}

// ---------------- 3x3 Householder QR (LAPACK dlarfg convention) ----------------
__device__ __forceinline__ void qr3(const float A0[9], float Q[9]) {
    float a[9];
#pragma unroll
    for (int i = 0; i < 9; i++) a[i] = A0[i];

    float tau1 = 0.f, v1 = 0.f, v2 = 0.f;
    {
        float c0 = a[0], c1 = a[3], c2 = a[6];
        float xn2 = c1 * c1 + c2 * c2;
        if (xn2 > 0.f) {
            float nrm  = sqrtf(c0 * c0 + xn2);
            float beta = -copysignf(nrm, c0);
            tau1 = (beta - c0) / beta;
            float inv = 1.f / (c0 - beta);
            v1 = c1 * inv;
            v2 = c2 * inv;
            // apply H1 to trailing columns
#pragma unroll
            for (int c = 1; c < 3; c++) {
                float w = a[c] + v1 * a[3 + c] + v2 * a[6 + c];
                w *= tau1;
                a[c]     -= w;
                a[3 + c] -= w * v1;
                a[6 + c] -= w * v2;
            }
        }
    }
    float tau2 = 0.f, u2 = 0.f;
    {
        float alpha = a[4], x2 = a[7];
        if (x2 != 0.f) {
            float nrm  = sqrtf(alpha * alpha + x2 * x2);
            float beta = -copysignf(nrm, alpha);
            tau2 = (beta - alpha) / beta;
            u2   = x2 / (alpha - beta);
        }
    }
    float h11 = 1.f - tau2;
    float h12 = -tau2 * u2;
    float h22 = 1.f - tau2 * u2 * u2;
    // H2 = [[1,0,0],[0,h11,h12],[0,h12,h22]];  Q = H1 * H2, H1 = I - tau1 v v^T, v=(1,v1,v2)
#pragma unroll
    for (int j = 0; j < 3; j++) {
        float h0 = (j == 0) ? 1.f : 0.f;
        float h1 = (j == 0) ? 0.f : ((j == 1) ? h11 : h12);
        float h2 = (j == 0) ? 0.f : ((j == 1) ? h12 : h22);
        float w  = tau1 * (h0 + v1 * h1 + v2 * h2);
        Q[0 * 3 + j] = h0 - w;
        Q[1 * 3 + j] = h1 - v1 * w;
        Q[2 * 3 + j] = h2 - v2 * w;
    }
}

// ---------------- per-node epilogue: projections + pos/R/t update ----------------
__global__ __launch_bounds__(256) void node_update_kernel(
        const float* __restrict__ out,
        const float* __restrict__ Wc, const float* __restrict__ bc,
        const float* __restrict__ WR, const float* __restrict__ bR,
        const float* __restrict__ Wt, const float* __restrict__ bt,
        float* __restrict__ pos, float* __restrict__ R, float* __restrict__ tv, int n) {
    __shared__ float sWp[13][D];   // 0:Wc, 1..9:WR, 10..12:Wt  (stored as [proj][k])
    int t = threadIdx.x;
    for (int i = t; i < 13 * D; i += 256) {
        int j = i >> 7, k = i & 127;
        float v;
        if (j == 0)      v = Wc[k];
        else if (j < 10) v = WR[k * 9 + (j - 1)];
        else             v = Wt[k * 3 + (j - 10)];
        sWp[j][k] = v;
    }
    __syncthreads();

    int node = blockIdx.x * 8 + (t >> 5);
    int lane = t & 31;
    if (node >= n) return;

    float4 xv = *(const float4*)&out[(size_t)node * D + lane * 4];
    float p[13];
#pragma unroll
    for (int j = 0; j < 13; j++) {
        float4 w = ((const float4*)&sWp[j][0])[lane];
        float s = xv.x * w.x + xv.y * w.y + xv.z * w.z + xv.w * w.w;
        s += __shfl_xor_sync(0xFFFFFFFF, s, 16);
        s += __shfl_xor_sync(0xFFFFFFFF, s, 8);
        s += __shfl_xor_sync(0xFFFFFFFF, s, 4);
        s += __shfl_xor_sync(0xFFFFFFFF, s, 2);
        s += __shfl_xor_sync(0xFFFFFFFF, s, 1);
        p[j] = s;
    }

    if (lane == 0) {
        // pos += broadcast(out@Wc + bc)
        float c = p[0] + bc[0];
        pos[node * 3 + 0] += c;
        pos[node * 3 + 1] += c;
        pos[node * 3 + 2] += c;
        // t += out@Wt + bt
        tv[node * 3 + 0] += p[10] + bt[0];
        tv[node * 3 + 1] += p[11] + bt[1];
        tv[node * 3 + 2] += p[12] + bt[2];
        // R = qr(out@WR + bR).Q @ R
        float Aq[9], Q[9];
#pragma unroll
        for (int i = 0; i < 9; i++) Aq[i] = p[1 + i] + bR[i];
        qr3(Aq, Q);
        float Ro[9];
#pragma unroll
        for (int i = 0; i < 9; i++) Ro[i] = R[(size_t)node * 9 + i];
        float Rn[9];
#pragma unroll
        for (int i = 0; i < 3; i++)
#pragma unroll
            for (int j = 0; j < 3; j++)
                Rn[i * 3 + j] = Q[i * 3 + 0] * Ro[0 * 3 + j]
                              + Q[i * 3 + 1] * Ro[1 * 3 + j]
                              + Q[i * 3 + 2] * Ro[2 * 3 + j];
#pragma unroll
        for (int i = 0; i < 9; i++) R[(size_t)node * 9 + i] = Rn[i];
    }
}

// ---------------- launch ----------------
extern "C" void kernel_launch(void* const* d_in, const int* in_sizes, int n_in,
                              void* d_out, int out_size) {
    const float* x   = (const float*)d_in[0];
    const float* pos = (const float*)d_in[1];
    const int*   ei  = (const int*)d_in[2];
    const float* Wl  = (const float*)d_in[3];
    const float* bl  = (const float*)d_in[4];
    const float* Wc  = (const float*)d_in[5];
    const float* bc  = (const float*)d_in[6];
    const float* WR  = (const float*)d_in[7];
    const float* bR  = (const float*)d_in[8];
    const float* Wt  = (const float*)d_in[9];
    const float* bt  = (const float*)d_in[10];
    const float* Wf  = (const float*)d_in[11];
    const float* bf  = (const float*)d_in[12];

    int n = in_sizes[0] / D;
    int E = in_sizes[2] / 2;
    const int* src = ei;
    const int* dst = ei + E;

    float* zout = (float*)d_out;
    float* pout = zout + (size_t)n * D;
    float* Rout = pout + (size_t)n * 3;
    float* tout = Rout + (size_t)n * 9;

    float *agg, *xb, *deg;
    cudaGetSymbolAddress((void**)&agg, g_agg);
    cudaGetSymbolAddress((void**)&xb,  g_x);
    cudaGetSymbolAddress((void**)&deg, g_deg);

    // init outputs / degree
    cudaMemsetAsync(deg, 0, (size_t)n * sizeof(float), 0);
    count_deg_kernel<<<(E + 255) / 256, 256>>>(dst, deg, E);
    init_R_kernel<<<(n + 255) / 256, 256>>>(Rout, n);
    cudaMemsetAsync(tout, 0, (size_t)n * 3 * sizeof(float), 0);
    cudaMemcpyAsync(pout, pos, (size_t)n * 3 * sizeof(float), cudaMemcpyDeviceToDevice, 0);

    const float* xcur = x;
    for (int l = 0; l < NLAYERS; l++) {
        cudaMemsetAsync(agg, 0, (size_t)n * D * sizeof(float), 0);
        long long nthreads = (long long)E * 32;
        scatter_kernel<<<(int)((nthreads + 255) / 256), 256>>>(
            (const float4*)xcur, src, dst, (float4*)agg, E);
        gemm_kernel<<<(n + 127) / 128, 256>>>(agg, Wl + (size_t)l * D * D, bl + (size_t)l * D,
                                              deg, xb, n);
        node_update_kernel<<<(n + 7) / 8, 256>>>(xb,
            Wc + (size_t)l * D,      bc + l,
            WR + (size_t)l * D * 9,  bR + (size_t)l * 9,
            Wt + (size_t)l * D * 3,  bt + (size_t)l * 3,
            pout, Rout, tout, n);
        xcur = xb;
    }
    gemm_kernel<<<(n + 127) / 128, 256>>>(xb, Wf, bf, nullptr, zout, n);
}

// round 3
// speedup vs baseline: 1.1552x; 1.1552x over previous
#include <cuda_runtime.h>
#include <cstdint>

#define D        128
#define CD       3
#define NLAYERS  3
#define MAXN     65536
#define MAXE     1048576

// ---------------- scratch (no allocations allowed) ----------------
__device__ float g_agg [(size_t)MAXN * D];
__device__ float g_x   [(size_t)MAXN * D];
__device__ float g_deg [MAXN];
__device__ int   g_cnt [MAXN];
__device__ int   g_off [MAXN + 1];
__device__ int   g_srcs[MAXE];

// ---------------- CSR build ----------------
__global__ void hist_kernel(const int* __restrict__ dst, int* __restrict__ cnt, int E) {
    int i = blockIdx.x * blockDim.x + threadIdx.x;
    if (i < E) atomicAdd(&cnt[dst[i]], 1);
}

__global__ __launch_bounds__(1024) void scan_kernel(int* __restrict__ cnt, int* __restrict__ off,
                                                    float* __restrict__ deg, int n, int E) {
    __shared__ int ssum[1024];
    int t = threadIdx.x;
    int C = (n + 1023) / 1024;
    int lo = t * C, hi = min(lo + C, n);
    int s = 0;
    for (int i = lo; i < hi; i++) s += cnt[i];
    ssum[t] = s;
    __syncthreads();
    // Hillis-Steele inclusive scan
    for (int d = 1; d < 1024; d <<= 1) {
        int v = (t >= d) ? ssum[t - d] : 0;
        __syncthreads();
        ssum[t] += v;
        __syncthreads();
    }
    int base = ssum[t] - s;   // exclusive
    for (int i = lo; i < hi; i++) {
        int c = cnt[i];
        off[i] = base;
        deg[i] = (float)c;
        cnt[i] = 0;           // reset -> reused as cursor in fill
        base += c;
    }
    if (t == 1023) off[n] = E;
}

__global__ void fill_kernel(const int* __restrict__ src, const int* __restrict__ dst,
                            const int* __restrict__ off, int* __restrict__ cur,
                            int* __restrict__ srcs, int E) {
    int e = blockIdx.x * blockDim.x + threadIdx.x;
    if (e >= E) return;
    int d = dst[e];
    int p = atomicAdd(&cur[d], 1);
    srcs[off[d] + p] = src[e];
}

// ---------------- gather aggregation: agg[i] = sum_{e: dst=i} x[src[e]] ----------------
__global__ __launch_bounds__(256) void aggregate_kernel(
        const float4* __restrict__ x, const int* __restrict__ off,
        const int* __restrict__ srcs, float4* __restrict__ agg, int n) {
    int node = blockIdx.x * 8 + (threadIdx.x >> 5);
    if (node >= n) return;
    int lane = threadIdx.x & 31;
    int j0 = __ldg(&off[node]);
    int j1 = __ldg(&off[node + 1]);

    float4 acc = make_float4(0.f, 0.f, 0.f, 0.f);
    int j = j0;
    for (; j + 4 <= j1; j += 4) {
        int s0 = __ldg(&srcs[j + 0]);
        int s1 = __ldg(&srcs[j + 1]);
        int s2 = __ldg(&srcs[j + 2]);
        int s3 = __ldg(&srcs[j + 3]);
        float4 v0 = __ldg(&x[(size_t)s0 * 32 + lane]);
        float4 v1 = __ldg(&x[(size_t)s1 * 32 + lane]);
        float4 v2 = __ldg(&x[(size_t)s2 * 32 + lane]);
        float4 v3 = __ldg(&x[(size_t)s3 * 32 + lane]);
        acc.x += v0.x + v1.x + v2.x + v3.x;
        acc.y += v0.y + v1.y + v2.y + v3.y;
        acc.z += v0.z + v1.z + v2.z + v3.z;
        acc.w += v0.w + v1.w + v2.w + v3.w;
    }
    for (; j < j1; j++) {
        int s = __ldg(&srcs[j]);
        float4 v = __ldg(&x[(size_t)s * 32 + lane]);
        acc.x += v.x; acc.y += v.y; acc.z += v.z; acc.w += v.w;
    }
    agg[(size_t)node * 32 + lane] = acc;
}

// ---------------- R init (identity) ----------------
__global__ void init_R_kernel(float* __restrict__ R, int n) {
    int i = blockIdx.x * blockDim.x + threadIdx.x;
    if (i < n) {
        float* r = R + (size_t)i * 9;
        r[0] = 1.f; r[1] = 0.f; r[2] = 0.f;
        r[3] = 0.f; r[4] = 1.f; r[5] = 0.f;
        r[6] = 0.f; r[7] = 0.f; r[8] = 1.f;
    }
}

// ---------------- GEMM: out = A(n x 128) @ W(128 x 128) + (deg? deg[r]*bias : bias) ----------------
#define BK 32
__global__ __launch_bounds__(256) void gemm_kernel(
        const float* __restrict__ A, const float* __restrict__ W,
        const float* __restrict__ bias, const float* __restrict__ deg,
        float* __restrict__ out, int n) {
    __shared__ float sA[BK][D + 4];   // transposed: sA[k][r]
    __shared__ float sW[BK][D];

    int t    = threadIdx.x;
    int row0 = blockIdx.x * 128;
    int tx   = t & 15;
    int ty   = t >> 4;
    int rb   = ty * 8;
    int cb   = tx * 8;

    float acc[8][8];
#pragma unroll
    for (int i = 0; i < 8; i++)
#pragma unroll
        for (int j = 0; j < 8; j++) acc[i][j] = 0.f;

    int la_k = (t & 7) * 4;
    int la_r = t >> 3;
    int lw_k = t >> 3;
    int lw_c = (t & 7) * 4;

#pragma unroll 1
    for (int k0 = 0; k0 < D; k0 += BK) {
#pragma unroll
        for (int rr = 0; rr < 128; rr += 32) {
            int rloc = la_r + rr;
            int rg   = row0 + rloc;
            float4 v = make_float4(0.f, 0.f, 0.f, 0.f);
            if (rg < n) v = *(const float4*)&A[(size_t)rg * D + k0 + la_k];
            sA[la_k + 0][rloc] = v.x;
            sA[la_k + 1][rloc] = v.y;
            sA[la_k + 2][rloc] = v.z;
            sA[la_k + 3][rloc] = v.w;
        }
#pragma unroll
        for (int q = 0; q < 4; q++) {
            int c = lw_c + q * 32;
            *(float4*)&sW[lw_k][c] = *(const float4*)&W[(size_t)(k0 + lw_k) * D + c];
        }
        __syncthreads();

#pragma unroll
        for (int kk = 0; kk < BK; kk++) {
            float a[8], b[8];
            *(float4*)&a[0] = *(const float4*)&sA[kk][rb];
            *(float4*)&a[4] = *(const float4*)&sA[kk][rb + 4];
            *(float4*)&b[0] = *(const float4*)&sW[kk][cb];
            *(float4*)&b[4] = *(const float4*)&sW[kk][cb + 4];
#pragma unroll
            for (int i = 0; i < 8; i++)
#pragma unroll
                for (int j = 0; j < 8; j++) acc[i][j] += a[i] * b[j];
        }
        __syncthreads();
    }

    float bfrag[8];
#pragma unroll
    for (int j = 0; j < 8; j++) bfrag[j] = bias[cb + j];

#pragma unroll
    for (int i = 0; i < 8; i++) {
        int r = row0 + rb + i;
        if (r < n) {
            float f = deg ? deg[r] : 1.0f;
            float4 o0, o1;
            o0.x = acc[i][0] + f * bfrag[0];
            o0.y = acc[i][1] + f * bfrag[1];
            o0.z = acc[i][2] + f * bfrag[2];
            o0.w = acc[i][3] + f * bfrag[3];
            o1.x = acc[i][4] + f * bfrag[4];
            o1.y = acc[i][5] + f * bfrag[5];
            o1.z = acc[i][6] + f * bfrag[6];
            o1.w = acc[i][7] + f * bfrag[7];
            *(float4*)&out[(size_t)r * D + cb]     = o0;
            *(float4*)&out[(size_t)r * D + cb + 4] = o1;
        }
    }
}

// ---------------- 3x3 Householder QR (LAPACK dlarfg convention) ----------------
__device__ __forceinline__ void qr3(const float A0[9], float Q[9]) {
    float a[9];
#pragma unroll
    for (int i = 0; i < 9; i++) a[i] = A0[i];

    float tau1 = 0.f, v1 = 0.f, v2 = 0.f;
    {
        float c0 = a[0], c1 = a[3], c2 = a[6];
        float xn2 = c1 * c1 + c2 * c2;
        if (xn2 > 0.f) {
            float nrm  = sqrtf(c0 * c0 + xn2);
            float beta = -copysignf(nrm, c0);
            tau1 = (beta - c0) / beta;
            float inv = 1.f / (c0 - beta);
            v1 = c1 * inv;
            v2 = c2 * inv;
#pragma unroll
            for (int c = 1; c < 3; c++) {
                float w = a[c] + v1 * a[3 + c] + v2 * a[6 + c];
                w *= tau1;
                a[c]     -= w;
                a[3 + c] -= w * v1;
                a[6 + c] -= w * v2;
            }
        }
    }
    float tau2 = 0.f, u2 = 0.f;
    {
        float alpha = a[4], x2 = a[7];
        if (x2 != 0.f) {
            float nrm  = sqrtf(alpha * alpha + x2 * x2);
            float beta = -copysignf(nrm, alpha);
            tau2 = (beta - alpha) / beta;
            u2   = x2 / (alpha - beta);
        }
    }
    float h11 = 1.f - tau2;
    float h12 = -tau2 * u2;
    float h22 = 1.f - tau2 * u2 * u2;
#pragma unroll
    for (int j = 0; j < 3; j++) {
        float h0 = (j == 0) ? 1.f : 0.f;
        float h1 = (j == 0) ? 0.f : ((j == 1) ? h11 : h12);
        float h2 = (j == 0) ? 0.f : ((j == 1) ? h12 : h22);
        float w  = tau1 * (h0 + v1 * h1 + v2 * h2);
        Q[0 * 3 + j] = h0 - w;
        Q[1 * 3 + j] = h1 - v1 * w;
        Q[2 * 3 + j] = h2 - v2 * w;
    }
}

// ---------------- per-node epilogue: projections + pos/R/t update ----------------
__global__ __launch_bounds__(256) void node_update_kernel(
        const float* __restrict__ out,
        const float* __restrict__ Wc, const float* __restrict__ bc,
        const float* __restrict__ WR, const float* __restrict__ bR,
        const float* __restrict__ Wt, const float* __restrict__ bt,
        float* __restrict__ pos, float* __restrict__ R, float* __restrict__ tv, int n) {
    __shared__ float sWp[13][D];
    int t = threadIdx.x;
    for (int i = t; i < 13 * D; i += 256) {
        int j = i >> 7, k = i & 127;
        float v;
        if (j == 0)      v = Wc[k];
        else if (j < 10) v = WR[k * 9 + (j - 1)];
        else             v = Wt[k * 3 + (j - 10)];
        sWp[j][k] = v;
    }
    __syncthreads();

    int node = blockIdx.x * 8 + (t >> 5);
    int lane = t & 31;
    if (node >= n) return;

    float4 xv = *(const float4*)&out[(size_t)node * D + lane * 4];
    float p[13];
#pragma unroll
    for (int j = 0; j < 13; j++) {
        float4 w = ((const float4*)&sWp[j][0])[lane];
        float s = xv.x * w.x + xv.y * w.y + xv.z * w.z + xv.w * w.w;
        s += __shfl_xor_sync(0xFFFFFFFF, s, 16);
        s += __shfl_xor_sync(0xFFFFFFFF, s, 8);
        s += __shfl_xor_sync(0xFFFFFFFF, s, 4);
        s += __shfl_xor_sync(0xFFFFFFFF, s, 2);
        s += __shfl_xor_sync(0xFFFFFFFF, s, 1);
        p[j] = s;
    }

    if (lane == 0) {
        float c = p[0] + bc[0];
        pos[node * 3 + 0] += c;
        pos[node * 3 + 1] += c;
        pos[node * 3 + 2] += c;
        tv[node * 3 + 0] += p[10] + bt[0];
        tv[node * 3 + 1] += p[11] + bt[1];
        tv[node * 3 + 2] += p[12] + bt[2];
        float Aq[9], Q[9];
#pragma unroll
        for (int i = 0; i < 9; i++) Aq[i] = p[1 + i] + bR[i];
        qr3(Aq, Q);
        float Ro[9];
#pragma unroll
        for (int i = 0; i < 9; i++) Ro[i] = R[(size_t)node * 9 + i];
        float Rn[9];
#pragma unroll
        for (int i = 0; i < 3; i++)
#pragma unroll
            for (int j = 0; j < 3; j++)
                Rn[i * 3 + j] = Q[i * 3 + 0] * Ro[0 * 3 + j]
                              + Q[i * 3 + 1] * Ro[1 * 3 + j]
                              + Q[i * 3 + 2] * Ro[2 * 3 + j];
#pragma unroll
        for (int i = 0; i < 9; i++) R[(size_t)node * 9 + i] = Rn[i];
    }
}

// ---------------- launch ----------------
extern "C" void kernel_launch(void* const* d_in, const int* in_sizes, int n_in,
                              void* d_out, int out_size) {
    const float* x   = (const float*)d_in[0];
    const float* pos = (const float*)d_in[1];
    const int*   ei  = (const int*)d_in[2];
    const float* Wl  = (const float*)d_in[3];
    const float* bl  = (const float*)d_in[4];
    const float* Wc  = (const float*)d_in[5];
    const float* bc  = (const float*)d_in[6];
    const float* WR  = (const float*)d_in[7];
    const float* bR  = (const float*)d_in[8];
    const float* Wt  = (const float*)d_in[9];
    const float* bt  = (const float*)d_in[10];
    const float* Wf  = (const float*)d_in[11];
    const float* bf  = (const float*)d_in[12];

    int n = in_sizes[0] / D;
    int E = in_sizes[2] / 2;
    const int* src = ei;
    const int* dst = ei + E;

    float* zout = (float*)d_out;
    float* pout = zout + (size_t)n * D;
    float* Rout = pout + (size_t)n * 3;
    float* tout = Rout + (size_t)n * 9;

    float *agg, *xb, *deg;
    int *cnt, *off, *srcs;
    cudaGetSymbolAddress((void**)&agg,  g_agg);
    cudaGetSymbolAddress((void**)&xb,   g_x);
    cudaGetSymbolAddress((void**)&deg,  g_deg);
    cudaGetSymbolAddress((void**)&cnt,  g_cnt);
    cudaGetSymbolAddress((void**)&off,  g_off);
    cudaGetSymbolAddress((void**)&srcs, g_srcs);

    // ---- CSR build (once per call, reused for all layers) ----
    cudaMemsetAsync(cnt, 0, (size_t)n * sizeof(int), 0);
    hist_kernel<<<(E + 255) / 256, 256>>>(dst, cnt, E);
    scan_kernel<<<1, 1024>>>(cnt, off, deg, n, E);
    fill_kernel<<<(E + 255) / 256, 256>>>(src, dst, off, cnt, srcs, E);

    // ---- output init ----
    init_R_kernel<<<(n + 255) / 256, 256>>>(Rout, n);
    cudaMemsetAsync(tout, 0, (size_t)n * 3 * sizeof(float), 0);
    cudaMemcpyAsync(pout, pos, (size_t)n * 3 * sizeof(float), cudaMemcpyDeviceToDevice, 0);

    const float* xcur = x;
    for (int l = 0; l < NLAYERS; l++) {
        aggregate_kernel<<<(n + 7) / 8, 256>>>((const float4*)xcur, off, srcs, (float4*)agg, n);
        gemm_kernel<<<(n + 127) / 128, 256>>>(agg, Wl + (size_t)l * D * D, bl + (size_t)l * D,
                                              deg, xb, n);
        node_update_kernel<<<(n + 7) / 8, 256>>>(xb,
            Wc + (size_t)l * D,      bc + l,
            WR + (size_t)l * D * 9,  bR + (size_t)l * 9,
            Wt + (size_t)l * D * 3,  bt + (size_t)l * 3,
            pout, Rout, tout, n);
        xcur = xb;
    }
    gemm_kernel<<<(n + 127) / 128, 256>>>(xb, Wf, bf, nullptr, zout, n);
}